// round 12
// baseline (speedup 1.0000x reference)
#include <cuda_runtime.h>
#include <math.h>
#include <float.h>

#define BB   2
#define NP   16384
#define FF   32
#define MM   4096
#define KK   64
#define HH   64
#define CO   128
#define NTOT (BB*NP)
#define MTOT (BB*MM)
#define CANDMAX 2048
#define NBIN 2048

#define GFPS  8                 // CTAs per cloud (one cluster)  [R7/R11 proven config]
#define CWARPS 8
#define TFPS  (CWARPS*32)       // 256 threads
#define SHARD (NP/GFPS)
#define PPT   (SHARD/TFPS)      // 8
#define NSLOT (GFPS*CWARPS)     // 64

#define GG    8
#define CELLS (GG*GG*GG)
#define CAP   128               // padded cell capacity (avg fill 32)

#define NFPSB (BB*GFPS)         // 16 FPS blocks (wave-1 by CLC contiguous placement)
#define NHELP 240               // helper blocks (feat + grid scatter)
#define NBLK  (NFPSB + NHELP)   // 256, multiple of cluster width 8
#define PERH  144               // points per helper block (multiple of 4)

static __device__ float g_pc[MTOT*3];
static __device__ float g_u[NTOT*HH];
// padded-cell spatial grid (scan-free)
static __device__ int   g_cellcnt[BB*CELLS];
static __device__ float g_cgx[BB*CELLS*CAP];
static __device__ float g_cgy[BB*CELLS*CAP];
static __device__ float g_cgz[BB*CELLS*CAP];
static __device__ int   g_cgidx[BB*CELLS*CAP];

typedef unsigned long long ull;

// ---------- packed f32x2 helpers (lane-wise identical rounding to scalar fp32) ----------
__device__ __forceinline__ ull pack2(float lo, float hi) {
    ull r;
    asm("mov.b64 %0, {%1, %2};" : "=l"(r) : "r"(__float_as_uint(lo)), "r"(__float_as_uint(hi)));
    return r;
}
__device__ __forceinline__ void unpack2(ull v, float &lo, float &hi) {
    unsigned a, b;
    asm("mov.b64 {%0, %1}, %2;" : "=r"(a), "=r"(b) : "l"(v));
    lo = __uint_as_float(a); hi = __uint_as_float(b);
}
__device__ __forceinline__ ull add2(ull a, ull b) {
    ull r; asm("add.rn.f32x2 %0, %1, %2;" : "=l"(r) : "l"(a), "l"(b)); return r;
}
__device__ __forceinline__ ull mul2(ull a, ull b) {
    ull r; asm("mul.rn.f32x2 %0, %1, %2;" : "=l"(r) : "l"(a), "l"(b)); return r;
}
__device__ __forceinline__ ull fma2(ull a, ull b, ull c) {
    ull r; asm("fma.rn.f32x2 %0, %1, %2, %3;" : "=l"(r) : "l"(a), "l"(b), "l"(c)); return r;
}

// ---------- cluster / smem sync helpers ----------
__device__ __forceinline__ unsigned cta_rank() {
    unsigned r; asm("mov.u32 %0, %%cluster_ctarank;" : "=r"(r)); return r;
}
__device__ __forceinline__ void cluster_sync_all() {
    asm volatile("barrier.cluster.arrive.aligned;" ::: "memory");
    asm volatile("barrier.cluster.wait.aligned;" ::: "memory");
}
__device__ __forceinline__ unsigned mapa_addr(unsigned local_smem_addr, unsigned target_rank) {
    unsigned raddr;
    asm volatile("mapa.shared::cluster.u32 %0, %1, %2;" : "=r"(raddr)
                 : "r"(local_smem_addr), "r"(target_rank));
    return raddr;
}
__device__ __forceinline__ void st_cluster_relaxed_u64(unsigned remote_addr, ull v) {
    asm volatile("st.relaxed.cluster.shared::cluster.b64 [%0], %1;"
                 :: "r"(remote_addr), "l"(v) : "memory");
}
__device__ __forceinline__ void ld_smem_volatile_v2(unsigned addr, ull &a, ull &b) {
    asm volatile("ld.volatile.shared.v2.u64 {%0, %1}, [%2];"
                 : "=l"(a), "=l"(b) : "r"(addr) : "memory");
}

__device__ __forceinline__ int cell_of(float x, float y, float z) {
    int cx = min(GG-1, max(0, (int)(x * (float)GG)));
    int cy = min(GG-1, max(0, (int)(y * (float)GG)));
    int cz = min(GG-1, max(0, (int)(z * (float)GG)));
    return (cz*GG + cy)*GG + cx;
}

// =====================================================================================
// zero kernel: reset cell counters (every launch -> replay-deterministic)
// =====================================================================================
__global__ void zero_kernel() {
    g_cellcnt[blockIdx.x * 256 + threadIdx.x] = 0;
}

// =====================================================================================
// FUSED launch: blocks 0..15 = exact FPS (R11 code, UNCHANGED, no cross-role deps);
// blocks 16..255 = helpers: per-point layer-1 partials (feat) + padded-cell scatter.
// Helpers depend only on kernel inputs — zero synchronization with FPS.
// =====================================================================================
__global__ __launch_bounds__(TFPS, 1) __cluster_dims__(GFPS, 1, 1)
void fps_feat_kernel(const float* __restrict__ pos,
                     const float* __restrict__ xin,
                     const float* __restrict__ W1,
                     const float* __restrict__ b1) {
    extern __shared__ float sh[];
    __shared__ __align__(16) ull slot[2][NSLOT];
    __shared__ float xs[4][FF];
    __shared__ float ps[4][3];

    const int tid = threadIdx.x, lane = tid & 31, wid = tid >> 5;

    if (blockIdx.x >= NFPSB) {
        // ============================ helper role ============================
        const int eb = blockIdx.x - NFPSB;
        const int j0 = eb * PERH;
        if (j0 >= NTOT) return;
        const int j1 = min(j0 + PERH, NTOT);
        // feat: groups of 4 points, 256 threads = 4 points x 64 channels
        for (int g = j0; g < j1; g += 4) {
            if (tid < 128) xs[tid >> 5][tid & 31] = xin[(size_t)(g + (tid >> 5))*FF + (tid & 31)];
            if (tid < 12)  ps[tid / 3][tid % 3]   = pos[(size_t)g*3 + tid];
            __syncthreads();
            const int pt = tid >> 6, h = tid & 63;
            float acc = b1[h];
#pragma unroll
            for (int f = 0; f < FF; ++f) acc += xs[pt][f] * W1[f*HH + h];
            acc += ps[pt][0] * W1[32*HH + h];
            acc += ps[pt][1] * W1[33*HH + h];
            acc += ps[pt][2] * W1[34*HH + h];
            g_u[(size_t)(g + pt)*HH + h] = acc;
            __syncthreads();
        }
        // padded-cell scatter (scan-free)
        for (int j = j0 + tid; j < j1; j += TFPS) {
            const int bb = j / NP, lj = j % NP;
            const float px = pos[3*j], py = pos[3*j+1], pz = pos[3*j+2];
            const int cell = bb*CELLS + cell_of(px, py, pz);
            const int s = atomicAdd(&g_cellcnt[cell], 1);
            if (s < CAP) {
                g_cgx[cell*CAP + s] = px;
                g_cgy[cell*CAP + s] = py;
                g_cgz[cell*CAP + s] = pz;
                g_cgidx[cell*CAP + s] = lj;
            }
        }
        return;
    }

    // ============================ FPS role (R11, unchanged) ============================
    float* sx = sh;
    float* sy = sh + NP;
    float* sz = sh + 2*NP;
    const unsigned rank = cta_rank();
    const int b = blockIdx.x / GFPS;
    const float* p = pos + (size_t)b * NP * 3;
    const unsigned slot_base = (unsigned)__cvta_generic_to_shared(&slot[0][0]);

    if (tid < 2*NSLOT) slot[tid >> 6][tid & 63] = ~0ull;
    for (int i = tid; i < NP; i += TFPS) {
        sx[i] = p[3*i]; sy[i] = p[3*i+1]; sz[i] = p[3*i+2];
    }
    __syncthreads();
    cluster_sync_all();

    unsigned raddr_g = 0;
    if (lane < GFPS)
        raddr_g = mapa_addr(slot_base + (rank*CWARPS + (unsigned)wid)*8u, (unsigned)lane);

    const int jbase = (int)rank * SHARD + tid;
    float mx[PPT], my[PPT], mz[PPT], d[PPT];
    const float x0 = sx[0], y0 = sy[0], z0 = sz[0];
    float bd = -FLT_MAX; int bj = 0;
#pragma unroll
    for (int k = 0; k < PPT; ++k) {
        int j = jbase + k*TFPS;
        mx[k] = sx[j]; my[k] = sy[j]; mz[k] = sz[j];
        float dx = __fsub_rn(mx[k], x0);
        float dy = __fsub_rn(my[k], y0);
        float dz = __fsub_rn(mz[k], z0);
        d[k] = __fadd_rn(__fadd_rn(__fmul_rn(dx,dx), __fmul_rn(dy,dy)), __fmul_rn(dz,dz));
        if (d[k] > bd) { bd = d[k]; bj = j; }
    }
    if (rank == 0 && tid == 0) {
        g_pc[((size_t)b*MM + 0)*3 + 0] = x0;
        g_pc[((size_t)b*MM + 0)*3 + 1] = y0;
        g_pc[((size_t)b*MM + 0)*3 + 2] = z0;
    }

    for (int m = 1; m < MM; ++m) {
        const int buf = m & 1;
        const unsigned mt = (unsigned)m;
        const unsigned boff = (unsigned)buf * (NSLOT*8u);
        const unsigned mb   = __float_as_uint(bd);
        const unsigned wmax = __reduce_max_sync(0xffffffffu, mb);
        const unsigned ci   = (mb == wmax) ? (unsigned)bj : 0xFFFFFFFFu;
        const unsigned widx = __reduce_min_sync(0xffffffffu, ci);
        const ull key = ((ull)mt << 46) | ((ull)wmax << 14) | widx;
        if (lane < GFPS) st_cluster_relaxed_u64(raddr_g + boff, key);
        const unsigned sa = slot_base + boff + (unsigned)lane * 16u;
        ull k0, k1;
        for (;;) {
            ld_smem_volatile_v2(sa, k0, k1);
            bool ok = ((unsigned)(k0 >> 46) == mt) & ((unsigned)(k1 >> 46) == mt);
            if (__all_sync(0xffffffffu, ok)) break;
        }
        const unsigned d0 = (unsigned)(k0 >> 14), d1 = (unsigned)(k1 >> 14);
        const unsigned i0 = (unsigned)(k0 & 0x3FFFull), i1 = (unsigned)(k1 & 0x3FFFull);
        unsigned dl, il;
        if (d0 > d1)      { dl = d0; il = i0; }
        else if (d1 > d0) { dl = d1; il = i1; }
        else              { dl = d0; il = min(i0, i1); }
        const unsigned wd = __reduce_max_sync(0xffffffffu, dl);
        const unsigned c2 = (dl == wd) ? il : 0xFFFFFFFFu;
        const unsigned wi = __reduce_min_sync(0xffffffffu, c2);
        const float wx = sx[wi], wy = sy[wi], wz = sz[wi];
        if (rank == 0 && tid == 0) {
            g_pc[((size_t)b*MM + m)*3 + 0] = wx;
            g_pc[((size_t)b*MM + m)*3 + 1] = wy;
            g_pc[((size_t)b*MM + m)*3 + 2] = wz;
        }
        const ull nwx = pack2(-wx, -wx);
        const ull nwy = pack2(-wy, -wy);
        const ull nwz = pack2(-wz, -wz);
        bd = -FLT_MAX; bj = 0;
#pragma unroll
        for (int kk = 0; kk < PPT/2; ++kk) {
            ull dx = add2(pack2(mx[2*kk], mx[2*kk+1]), nwx);
            ull dy = add2(pack2(my[2*kk], my[2*kk+1]), nwy);
            ull dz = add2(pack2(mz[2*kk], mz[2*kk+1]), nwz);
            ull s  = add2(add2(mul2(dx,dx), mul2(dy,dy)), mul2(dz,dz));
            float s0, s1; unpack2(s, s0, s1);
            d[2*kk]   = fminf(d[2*kk],   s0);
            d[2*kk+1] = fminf(d[2*kk+1], s1);
            if (d[2*kk]   > bd) { bd = d[2*kk];   bj = jbase + (2*kk)*TFPS; }
            if (d[2*kk+1] > bd) { bd = d[2*kk+1]; bj = jbase + (2*kk+1)*TFPS; }
        }
    }
    cluster_sync_all();
}

// =====================================================================================
// Kernel 3 (FUSED): grid-pruned ball query over padded cells (warp-per-row, counts
// prefetched lane-parallel), radix-select top-K, layer-2 MLP + max aggregation.
// =====================================================================================
__device__ __forceinline__ float dot64(const float* __restrict__ h1,
                                       const ull* __restrict__ w2p) {
    const float2* hb = (const float2*)h1;
    ull a0 = 0ull, a1 = 0ull;
#pragma unroll
    for (int h2 = 0; h2 < HH/2; h2 += 2) {
        float2 p0 = hb[h2], p1 = hb[h2 + 1];
        a0 = fma2(pack2(p0.x, p0.y), w2p[h2],     a0);
        a1 = fma2(pack2(p1.x, p1.y), w2p[h2 + 1], a1);
    }
    float l0, u0, l1, u1;
    unpack2(a0, l0, u0); unpack2(a1, l1, u1);
    return (l0 + u0) + (l1 + u1);
}

__global__ __launch_bounds__(256) void ballq_mlp_kernel(const float* __restrict__ W1,
                                                        const float* __restrict__ W2,
                                                        const float* __restrict__ b2,
                                                        float* __restrict__ out) {
    const float R2 = (float)(0.2 * 0.2);
    const int i = blockIdx.x;
    const int b = i / MM;
    __shared__ ull cand[CANDMAX];
    __shared__ int hist[NBIN];
    __shared__ ull tbuf[256];
    __shared__ int nbr[KK];
    __shared__ float vsh[HH];
    __shared__ float h1buf[4][HH];
    __shared__ float mxsh[128];
    __shared__ int cnt, outc, tcnt, tsel_s, nless_s, fincnt;
    __shared__ int wsum[8];
    const int tid = threadIdx.x;
    const int lane = tid & 31, w = tid >> 5;
    if (tid == 0) { cnt = 0; outc = 0; tcnt = 0; }
    const float cx = g_pc[(size_t)i*3 + 0];
    const float cy = g_pc[(size_t)i*3 + 1];
    const float cz = g_pc[(size_t)i*3 + 2];
    for (int t = tid; t < NBIN; t += 256) hist[t] = 0;
    if (tid < HH) {
        float icx = __fdiv_rn(cx, 0.2f);
        float icy = __fdiv_rn(cy, 0.2f);
        float icz = __fdiv_rn(cz, 0.2f);
        vsh[tid] = icx*W1[32*HH + tid] + icy*W1[33*HH + tid] + icz*W1[34*HH + tid];
    }
    __syncthreads();

    // grid-pruned candidate scan over padded cells, warp-per-row
    const float RW = 0.2001f;
    const int x0 = max(0, (int)floorf((cx - RW) * (float)GG));
    const int x1 = min(GG-1, (int)floorf((cx + RW) * (float)GG));
    const int y0 = max(0, (int)floorf((cy - RW) * (float)GG));
    const int y1 = min(GG-1, (int)floorf((cy + RW) * (float)GG));
    const int z0 = max(0, (int)floorf((cz - RW) * (float)GG));
    const int z1 = min(GG-1, (int)floorf((cz + RW) * (float)GG));
    const int ny = y1 - y0 + 1;
    const int nrows = (z1 - z0 + 1) * ny;
    for (int r = w; r < nrows; r += 8) {
        const int zz = z0 + r / ny;
        const int yy = y0 + r % ny;
        const int crow = b*CELLS + (zz*GG + yy)*GG;
        // lane-parallel prefetch of the row's cell counts
        int cc_l = 0;
        if (lane <= x1 - x0) cc_l = min(g_cellcnt[crow + x0 + lane], CAP);
        for (int cxx = x0; cxx <= x1; ++cxx) {
            const int cc = __shfl_sync(0xffffffffu, cc_l, cxx - x0);
            const int base = (crow + cxx) * CAP;
            for (int t = lane; t < cc; t += 32) {
                float dx = __fsub_rn(cx, g_cgx[base + t]);
                float dy = __fsub_rn(cy, g_cgy[base + t]);
                float dz = __fsub_rn(cz, g_cgz[base + t]);
                float d2 = __fadd_rn(__fadd_rn(__fmul_rn(dx,dx), __fmul_rn(dy,dy)), __fmul_rn(dz,dz));
                if (d2 <= R2) {
                    int sl = atomicAdd(&cnt, 1);
                    if (sl < CANDMAX)
                        cand[sl] = ((ull)__float_as_uint(d2) << 32) | (unsigned)g_cgidx[base + t];
                }
            }
        }
    }
    __syncthreads();
    const int c = min(cnt, CANDMAX);

    if (c <= KK) {
        for (int s = tid; s < c; s += 256) nbr[s] = (int)(unsigned)cand[s];
        if (tid == 0) fincnt = c;
    } else {
        for (int s = tid; s < c; s += 256)
            atomicAdd(&hist[(unsigned)(cand[s] >> 53)], 1);
        __syncthreads();
        const int base = tid * 8;
        int h[8]; int ssum = 0;
#pragma unroll
        for (int q = 0; q < 8; ++q) { h[q] = hist[base + q]; ssum += h[q]; }
        int v = ssum;
#pragma unroll
        for (int o = 1; o < 32; o <<= 1) {
            int n2 = __shfl_up_sync(0xffffffffu, v, o);
            if (lane >= o) v += n2;
        }
        if (lane == 31) wsum[w] = v;
        __syncthreads();
        if (tid == 0) {
            int a = 0;
#pragma unroll
            for (int q = 0; q < 8; ++q) { int t = wsum[q]; wsum[q] = a; a += t; }
        }
        __syncthreads();
        const int excl = v - ssum + wsum[w];
        if (excl < KK && KK <= excl + ssum) {
            int cum = excl;
#pragma unroll
            for (int q = 0; q < 8; ++q) {
                if (cum < KK && KK <= cum + h[q]) { tsel_s = base + q; nless_s = cum; }
                cum += h[q];
            }
        }
        __syncthreads();
        const int Tbin = tsel_s, nless = nless_s;
        for (int s = tid; s < c; s += 256) {
            const ull cv = cand[s];
            const int bin = (int)(unsigned)(cv >> 53);
            if (bin < Tbin) {
                int o = atomicAdd(&outc, 1);
                nbr[o] = (int)(unsigned)cv;
            } else if (bin == Tbin) {
                int t = atomicAdd(&tcnt, 1);
                if (t < 256) tbuf[t] = cv;
            }
        }
        __syncthreads();
        const int tc = tcnt;
        if (tc <= 256) {
            int p2 = 1; while (p2 < tc) p2 <<= 1;
            for (int t = tid; t < p2; t += 256)
                if (t >= tc) tbuf[t] = ~0ull;
            for (int k = 2; k <= p2; k <<= 1) {
                for (int s = k >> 1; s > 0; s >>= 1) {
                    __syncthreads();
                    for (int t = tid; t < p2; t += 256) {
                        int pr = t ^ s;
                        if (pr > t) {
                            ull a = tbuf[t], bv = tbuf[pr];
                            bool up = ((t & k) == 0);
                            if ((a > bv) == up) { tbuf[t] = bv; tbuf[pr] = a; }
                        }
                    }
                }
            }
            __syncthreads();
            const int need = KK - nless;
            if (tid < need) nbr[nless + tid] = (int)(unsigned)tbuf[tid];
        } else {
            int p2 = KK; while (p2 < c) p2 <<= 1;
            for (int t = tid; t < p2; t += 256)
                if (t >= c) cand[t] = ~0ull;
            for (int k = 2; k <= p2; k <<= 1) {
                for (int s = k >> 1; s > 0; s >>= 1) {
                    __syncthreads();
                    for (int t = tid; t < p2; t += 256) {
                        int pr = t ^ s;
                        if (pr > t) {
                            ull a = cand[t], bv = cand[pr];
                            bool up = ((t & k) == 0);
                            if ((a > bv) == up) { cand[t] = bv; cand[pr] = a; }
                        }
                    }
                }
            }
            __syncthreads();
            if (tid < KK) nbr[tid] = (int)(unsigned)cand[tid];
        }
        if (tid == 0) fincnt = KK;
    }
    __syncthreads();
    const int n = fincnt;

    // ---------------- MLP phase ----------------
    const int ch = tid & 127, half = tid >> 7;
    ull w2p[HH/2];
#pragma unroll
    for (int h = 0; h < HH/2; ++h)
        w2p[h] = pack2(W2[(size_t)(2*h)*CO + ch], W2[(size_t)(2*h + 1)*CO + ch]);

    float mxv = -FLT_MAX;
    for (int jj = 0; jj < n; jj += 4) {
        const int idx = jj + (tid >> 6);
        if (idx < n) {
            const int nb = nbr[idx];
            h1buf[tid >> 6][tid & 63] =
                fmaxf(g_u[((size_t)b*NP + nb)*HH + (tid & 63)] - vsh[tid & 63], 0.0f);
        }
        __syncthreads();
        const int r = half * 2;
        if (jj + r < n)     mxv = fmaxf(mxv, dot64(h1buf[r],     w2p));
        if (jj + r + 1 < n) mxv = fmaxf(mxv, dot64(h1buf[r + 1], w2p));
        __syncthreads();
    }
    if (half == 1) mxsh[ch] = mxv;
    __syncthreads();
    if (half == 0) {
        float o = (n > 1) ? fmaxf(mxv, mxsh[ch]) : mxv;
        out[(size_t)i*CO + ch] = (n > 0) ? (o + b2[ch]) : 0.0f;
    }
}

// =====================================================================================
// tail outputs
// =====================================================================================
__global__ void tail_kernel(float* __restrict__ out, int has_pc, int has_batch) {
    const int i = blockIdx.x * 256 + threadIdx.x;
    if (has_pc && i < MTOT*3) out[(size_t)MTOT*CO + i] = g_pc[i];
    if (has_batch && i < MTOT) out[(size_t)MTOT*CO + (size_t)MTOT*3 + i] = (float)(i / MM);
}

extern "C" void kernel_launch(void* const* d_in, const int* in_sizes, int n_in,
                              void* d_out, int out_size) {
    const float* x   = (const float*)d_in[0];
    const float* pos = (const float*)d_in[1];
    const float* W1  = (const float*)d_in[3];
    const float* b1  = (const float*)d_in[4];
    const float* W2  = (const float*)d_in[5];
    const float* b2  = (const float*)d_in[6];
    float* out = (float*)d_out;

    cudaFuncSetAttribute(fps_feat_kernel, cudaFuncAttributeMaxDynamicSharedMemorySize, 3*NP*4);

    zero_kernel<<<(BB*CELLS)/256, 256>>>();
    fps_feat_kernel<<<NBLK, TFPS, 3*NP*4>>>(pos, x, W1, b1);
    ballq_mlp_kernel<<<MTOT, 256>>>(W1, W2, b2, out);

    int has_pc    = out_size >= MTOT*CO + MTOT*3;
    int has_batch = out_size >= MTOT*CO + MTOT*3 + MTOT;
    if (has_pc)
        tail_kernel<<<(MTOT*3 + 255)/256, 256>>>(out, has_pc, has_batch);
}

// round 14
// speedup vs baseline: 1.0618x; 1.0618x over previous
#include <cuda_runtime.h>
#include <math.h>
#include <float.h>

#define BB   2
#define NP   16384
#define FF   32
#define MM   4096
#define KK   64
#define HH   64
#define CO   128
#define NTOT (BB*NP)
#define MTOT (BB*MM)
#define CANDMAX 2048
#define NBIN 2048

#define GFPS  8                 // CTAs per cloud (one cluster)  [R7/R11 proven config]
#define CWARPS 8
#define TFPS  (CWARPS*32)       // 256 threads
#define SHARD (NP/GFPS)
#define PPT   (SHARD/TFPS)      // 8
#define NSLOT (GFPS*CWARPS)     // 64

#define GG    8
#define CELLS (GG*GG*GG)

static __device__ float g_pc[MTOT*3];
static __device__ float g_u[NTOT*HH];
// spatial grid (CSR)
static __device__ int   g_ccnt[BB*CELLS];
static __device__ int   g_coff[BB*CELLS + 1];
static __device__ int   g_cfill[BB*CELLS];
static __device__ float g_gx[NTOT], g_gy[NTOT], g_gz[NTOT];
static __device__ int   g_gidx[NTOT];

typedef unsigned long long ull;

// ---------- packed f32x2 helpers (lane-wise identical rounding to scalar fp32) ----------
__device__ __forceinline__ ull pack2(float lo, float hi) {
    ull r;
    asm("mov.b64 %0, {%1, %2};" : "=l"(r) : "r"(__float_as_uint(lo)), "r"(__float_as_uint(hi)));
    return r;
}
__device__ __forceinline__ void unpack2(ull v, float &lo, float &hi) {
    unsigned a, b;
    asm("mov.b64 {%0, %1}, %2;" : "=r"(a), "=r"(b) : "l"(v));
    lo = __uint_as_float(a); hi = __uint_as_float(b);
}
__device__ __forceinline__ ull add2(ull a, ull b) {
    ull r; asm("add.rn.f32x2 %0, %1, %2;" : "=l"(r) : "l"(a), "l"(b)); return r;
}
__device__ __forceinline__ ull mul2(ull a, ull b) {
    ull r; asm("mul.rn.f32x2 %0, %1, %2;" : "=l"(r) : "l"(a), "l"(b)); return r;
}
__device__ __forceinline__ ull fma2(ull a, ull b, ull c) {
    ull r; asm("fma.rn.f32x2 %0, %1, %2, %3;" : "=l"(r) : "l"(a), "l"(b), "l"(c)); return r;
}

// ---------- cluster / smem sync helpers ----------
__device__ __forceinline__ unsigned cta_rank() {
    unsigned r; asm("mov.u32 %0, %%cluster_ctarank;" : "=r"(r)); return r;
}
__device__ __forceinline__ void cluster_sync_all() {
    asm volatile("barrier.cluster.arrive.aligned;" ::: "memory");
    asm volatile("barrier.cluster.wait.aligned;" ::: "memory");
}
__device__ __forceinline__ unsigned mapa_addr(unsigned local_smem_addr, unsigned target_rank) {
    unsigned raddr;
    asm volatile("mapa.shared::cluster.u32 %0, %1, %2;" : "=r"(raddr)
                 : "r"(local_smem_addr), "r"(target_rank));
    return raddr;
}
__device__ __forceinline__ void st_cluster_relaxed_u64(unsigned remote_addr, ull v) {
    asm volatile("st.relaxed.cluster.shared::cluster.b64 [%0], %1;"
                 :: "r"(remote_addr), "l"(v) : "memory");
}
__device__ __forceinline__ void ld_smem_volatile_v2(unsigned addr, ull &a, ull &b) {
    asm volatile("ld.volatile.shared.v2.u64 {%0, %1}, [%2];"
                 : "=l"(a), "=l"(b) : "r"(addr) : "memory");
}

// =====================================================================================
// Kernel 1: exact FPS — R11 proven configuration, UNCHANGED.
// =====================================================================================
__global__ __launch_bounds__(TFPS, 1) __cluster_dims__(GFPS, 1, 1)
void fps_kernel(const float* __restrict__ pos) {
    extern __shared__ float sh[];
    float* sx = sh;
    float* sy = sh + NP;
    float* sz = sh + 2*NP;
    __shared__ __align__(16) ull slot[2][NSLOT];

    const int tid = threadIdx.x, lane = tid & 31, wid = tid >> 5;
    const unsigned rank = cta_rank();
    const int b = blockIdx.x / GFPS;
    const float* p = pos + (size_t)b * NP * 3;

    const unsigned slot_base = (unsigned)__cvta_generic_to_shared(&slot[0][0]);

    if (tid < 2*NSLOT) slot[tid >> 6][tid & 63] = ~0ull;

    for (int i = tid; i < NP; i += TFPS) {
        sx[i] = p[3*i]; sy[i] = p[3*i+1]; sz[i] = p[3*i+2];
    }
    __syncthreads();
    cluster_sync_all();

    unsigned raddr_g = 0;
    if (lane < GFPS)
        raddr_g = mapa_addr(slot_base + (rank*CWARPS + (unsigned)wid)*8u, (unsigned)lane);

    const int jbase = (int)rank * SHARD + tid;
    float mx[PPT], my[PPT], mz[PPT], d[PPT];
    const float x0 = sx[0], y0 = sy[0], z0 = sz[0];
    float bd = -FLT_MAX; int bj = 0;
#pragma unroll
    for (int k = 0; k < PPT; ++k) {
        int j = jbase + k*TFPS;
        mx[k] = sx[j]; my[k] = sy[j]; mz[k] = sz[j];
        float dx = __fsub_rn(mx[k], x0);
        float dy = __fsub_rn(my[k], y0);
        float dz = __fsub_rn(mz[k], z0);
        d[k] = __fadd_rn(__fadd_rn(__fmul_rn(dx,dx), __fmul_rn(dy,dy)), __fmul_rn(dz,dz));
        if (d[k] > bd) { bd = d[k]; bj = j; }
    }
    if (rank == 0 && tid == 0) {
        g_pc[((size_t)b*MM + 0)*3 + 0] = x0;
        g_pc[((size_t)b*MM + 0)*3 + 1] = y0;
        g_pc[((size_t)b*MM + 0)*3 + 2] = z0;
    }

    for (int m = 1; m < MM; ++m) {
        const int buf = m & 1;
        const unsigned mt = (unsigned)m;
        const unsigned boff = (unsigned)buf * (NSLOT*8u);
        const unsigned mb   = __float_as_uint(bd);
        const unsigned wmax = __reduce_max_sync(0xffffffffu, mb);
        const unsigned ci   = (mb == wmax) ? (unsigned)bj : 0xFFFFFFFFu;
        const unsigned widx = __reduce_min_sync(0xffffffffu, ci);
        const ull key = ((ull)mt << 46) | ((ull)wmax << 14) | widx;
        if (lane < GFPS) st_cluster_relaxed_u64(raddr_g + boff, key);
        const unsigned sa = slot_base + boff + (unsigned)lane * 16u;
        ull k0, k1;
        for (;;) {
            ld_smem_volatile_v2(sa, k0, k1);
            bool ok = ((unsigned)(k0 >> 46) == mt) & ((unsigned)(k1 >> 46) == mt);
            if (__all_sync(0xffffffffu, ok)) break;
        }
        const unsigned d0 = (unsigned)(k0 >> 14), d1 = (unsigned)(k1 >> 14);
        const unsigned i0 = (unsigned)(k0 & 0x3FFFull), i1 = (unsigned)(k1 & 0x3FFFull);
        unsigned dl, il;
        if (d0 > d1)      { dl = d0; il = i0; }
        else if (d1 > d0) { dl = d1; il = i1; }
        else              { dl = d0; il = min(i0, i1); }
        const unsigned wd = __reduce_max_sync(0xffffffffu, dl);
        const unsigned c2 = (dl == wd) ? il : 0xFFFFFFFFu;
        const unsigned wi = __reduce_min_sync(0xffffffffu, c2);
        const float wx = sx[wi], wy = sy[wi], wz = sz[wi];
        if (rank == 0 && tid == 0) {
            g_pc[((size_t)b*MM + m)*3 + 0] = wx;
            g_pc[((size_t)b*MM + m)*3 + 1] = wy;
            g_pc[((size_t)b*MM + m)*3 + 2] = wz;
        }
        const ull nwx = pack2(-wx, -wx);
        const ull nwy = pack2(-wy, -wy);
        const ull nwz = pack2(-wz, -wz);
        bd = -FLT_MAX; bj = 0;
#pragma unroll
        for (int kk = 0; kk < PPT/2; ++kk) {
            ull dx = add2(pack2(mx[2*kk], mx[2*kk+1]), nwx);
            ull dy = add2(pack2(my[2*kk], my[2*kk+1]), nwy);
            ull dz = add2(pack2(mz[2*kk], mz[2*kk+1]), nwz);
            ull s  = add2(add2(mul2(dx,dx), mul2(dy,dy)), mul2(dz,dz));
            float s0, s1; unpack2(s, s0, s1);
            d[2*kk]   = fminf(d[2*kk],   s0);
            d[2*kk+1] = fminf(d[2*kk+1], s1);
            if (d[2*kk]   > bd) { bd = d[2*kk];   bj = jbase + (2*kk)*TFPS; }
            if (d[2*kk+1] > bd) { bd = d[2*kk+1]; bj = jbase + (2*kk+1)*TFPS; }
        }
    }
    cluster_sync_all();
}

// =====================================================================================
// Kernel 2: per-point layer-1 partials (unchanged)
// =====================================================================================
__global__ __launch_bounds__(256) void feat_kernel(const float* __restrict__ x,
                                                   const float* __restrict__ pos,
                                                   const float* __restrict__ W1,
                                                   const float* __restrict__ b1) {
    __shared__ float xs[4][FF];
    __shared__ float ps[4][3];
    const int j0 = blockIdx.x * 4;
    const int tid = threadIdx.x;
    if (tid < 128) xs[tid >> 5][tid & 31] = x[(size_t)(j0 + (tid >> 5))*FF + (tid & 31)];
    if (tid < 12)  ps[tid / 3][tid % 3]   = pos[(size_t)j0*3 + tid];
    __syncthreads();
    const int pt = tid >> 6, h = tid & 63;
    float acc = b1[h];
#pragma unroll
    for (int f = 0; f < FF; ++f) acc += xs[pt][f] * W1[f*HH + h];
    acc += ps[pt][0] * W1[32*HH + h];
    acc += ps[pt][1] * W1[33*HH + h];
    acc += ps[pt][2] * W1[34*HH + h];
    g_u[(size_t)(j0 + pt)*HH + h] = acc;
}

// =====================================================================================
// Spatial grid build (unchanged from R11)
// =====================================================================================
__device__ __forceinline__ int cell_of(float x, float y, float z) {
    int cx = min(GG-1, max(0, (int)(x * (float)GG)));
    int cy = min(GG-1, max(0, (int)(y * (float)GG)));
    int cz = min(GG-1, max(0, (int)(z * (float)GG)));
    return (cz*GG + cy)*GG + cx;
}
__global__ void grid_zero_kernel() {
    g_ccnt[blockIdx.x * 256 + threadIdx.x] = 0;
}
__global__ void grid_count_kernel(const float* __restrict__ pos) {
    const int j = blockIdx.x * 256 + threadIdx.x;
    const int b = j / NP;
    atomicAdd(&g_ccnt[b*CELLS + cell_of(pos[3*j], pos[3*j+1], pos[3*j+2])], 1);
}
__global__ __launch_bounds__(1024) void grid_scan_kernel() {
    __shared__ int wtot[32];
    const int tid = threadIdx.x;
    const int lane = tid & 31, w = tid >> 5;
    const int v = g_ccnt[tid];
    int s = v;
#pragma unroll
    for (int o = 1; o < 32; o <<= 1) {
        int n = __shfl_up_sync(0xffffffffu, s, o);
        if (lane >= o) s += n;
    }
    if (lane == 31) wtot[w] = s;
    __syncthreads();
    if (w == 0) {
        int t = wtot[lane], ts = t;
#pragma unroll
        for (int o = 1; o < 32; o <<= 1) {
            int n = __shfl_up_sync(0xffffffffu, ts, o);
            if (lane >= o) ts += n;
        }
        wtot[lane] = ts - t;
    }
    __syncthreads();
    const int excl = s - v + wtot[w];
    g_coff[tid] = excl;
    g_cfill[tid] = excl;
    if (tid == BB*CELLS - 1) g_coff[BB*CELLS] = excl + v;
}
__global__ void grid_scatter_kernel(const float* __restrict__ pos) {
    const int j = blockIdx.x * 256 + threadIdx.x;
    const int b = j / NP, lj = j % NP;
    const float x = pos[3*j], y = pos[3*j+1], z = pos[3*j+2];
    const int slot = atomicAdd(&g_cfill[b*CELLS + cell_of(x, y, z)], 1);
    g_gx[slot] = x; g_gy[slot] = y; g_gz[slot] = z; g_gidx[slot] = lj;
}

// =====================================================================================
// Kernel 3 (FUSED): grid-pruned ball query (warp-per-row) + radix-select + MLP/max.
// EXACT R11 code (proven 1932us / rel_err 1.1e-7).
// =====================================================================================
__device__ __forceinline__ float dot64(const float* __restrict__ h1,
                                       const ull* __restrict__ w2p) {
    const float2* hb = (const float2*)h1;
    ull a0 = 0ull, a1 = 0ull;
#pragma unroll
    for (int h2 = 0; h2 < HH/2; h2 += 2) {
        float2 p0 = hb[h2], p1 = hb[h2 + 1];
        a0 = fma2(pack2(p0.x, p0.y), w2p[h2],     a0);
        a1 = fma2(pack2(p1.x, p1.y), w2p[h2 + 1], a1);
    }
    float l0, u0, l1, u1;
    unpack2(a0, l0, u0); unpack2(a1, l1, u1);
    return (l0 + u0) + (l1 + u1);
}

__global__ __launch_bounds__(256) void ballq_mlp_kernel(const float* __restrict__ W1,
                                                        const float* __restrict__ W2,
                                                        const float* __restrict__ b2,
                                                        float* __restrict__ out) {
    const float R2 = (float)(0.2 * 0.2);
    const int i = blockIdx.x;
    const int b = i / MM;
    __shared__ ull cand[CANDMAX];
    __shared__ int hist[NBIN];
    __shared__ ull tbuf[256];
    __shared__ int nbr[KK];
    __shared__ float vsh[HH];
    __shared__ float h1buf[4][HH];
    __shared__ float mxsh[128];
    __shared__ int cnt, outc, tcnt, tsel_s, nless_s, fincnt;
    __shared__ int wsum[8];
    const int tid = threadIdx.x;
    const int lane = tid & 31, w = tid >> 5;
    if (tid == 0) { cnt = 0; outc = 0; tcnt = 0; }
    const float cx = g_pc[(size_t)i*3 + 0];
    const float cy = g_pc[(size_t)i*3 + 1];
    const float cz = g_pc[(size_t)i*3 + 2];
    for (int t = tid; t < NBIN; t += 256) hist[t] = 0;
    if (tid < HH) {
        float icx = __fdiv_rn(cx, 0.2f);
        float icy = __fdiv_rn(cy, 0.2f);
        float icz = __fdiv_rn(cz, 0.2f);
        vsh[tid] = icx*W1[32*HH + tid] + icy*W1[33*HH + tid] + icz*W1[34*HH + tid];
    }
    __syncthreads();

    // grid-pruned candidate scan, warp-per-row
    const float RW = 0.2001f;
    const int x0 = max(0, (int)floorf((cx - RW) * (float)GG));
    const int x1 = min(GG-1, (int)floorf((cx + RW) * (float)GG));
    const int y0 = max(0, (int)floorf((cy - RW) * (float)GG));
    const int y1 = min(GG-1, (int)floorf((cy + RW) * (float)GG));
    const int z0 = max(0, (int)floorf((cz - RW) * (float)GG));
    const int z1 = min(GG-1, (int)floorf((cz + RW) * (float)GG));
    const int ny = y1 - y0 + 1;
    const int nrows = (z1 - z0 + 1) * ny;
    for (int r = w; r < nrows; r += 8) {
        const int zz = z0 + r / ny;
        const int yy = y0 + r % ny;
        const int cbase = b*CELLS + (zz*GG + yy)*GG;
        const int s0 = g_coff[cbase + x0];
        const int e0 = g_coff[cbase + x1 + 1];
        for (int t = s0 + lane; t < e0; t += 32) {
            float dx = __fsub_rn(cx, g_gx[t]);
            float dy = __fsub_rn(cy, g_gy[t]);
            float dz = __fsub_rn(cz, g_gz[t]);
            float d2 = __fadd_rn(__fadd_rn(__fmul_rn(dx,dx), __fmul_rn(dy,dy)), __fmul_rn(dz,dz));
            if (d2 <= R2) {
                int sl = atomicAdd(&cnt, 1);
                if (sl < CANDMAX)
                    cand[sl] = ((ull)__float_as_uint(d2) << 32) | (unsigned)g_gidx[t];
            }
        }
    }
    __syncthreads();
    const int c = min(cnt, CANDMAX);

    if (c <= KK) {
        for (int s = tid; s < c; s += 256) nbr[s] = (int)(unsigned)cand[s];
        if (tid == 0) fincnt = c;
    } else {
        for (int s = tid; s < c; s += 256)
            atomicAdd(&hist[(unsigned)(cand[s] >> 53)], 1);
        __syncthreads();
        const int base = tid * 8;
        int h[8]; int ssum = 0;
#pragma unroll
        for (int q = 0; q < 8; ++q) { h[q] = hist[base + q]; ssum += h[q]; }
        int v = ssum;
#pragma unroll
        for (int o = 1; o < 32; o <<= 1) {
            int n2 = __shfl_up_sync(0xffffffffu, v, o);
            if (lane >= o) v += n2;
        }
        if (lane == 31) wsum[w] = v;
        __syncthreads();
        if (tid == 0) {
            int a = 0;
#pragma unroll
            for (int q = 0; q < 8; ++q) { int t = wsum[q]; wsum[q] = a; a += t; }
        }
        __syncthreads();
        const int excl = v - ssum + wsum[w];
        if (excl < KK && KK <= excl + ssum) {
            int cum = excl;
#pragma unroll
            for (int q = 0; q < 8; ++q) {
                if (cum < KK && KK <= cum + h[q]) { tsel_s = base + q; nless_s = cum; }
                cum += h[q];
            }
        }
        __syncthreads();
        const int Tbin = tsel_s, nless = nless_s;
        for (int s = tid; s < c; s += 256) {
            const ull cv = cand[s];
            const int bin = (int)(unsigned)(cv >> 53);
            if (bin < Tbin) {
                int o = atomicAdd(&outc, 1);
                nbr[o] = (int)(unsigned)cv;
            } else if (bin == Tbin) {
                int t = atomicAdd(&tcnt, 1);
                if (t < 256) tbuf[t] = cv;
            }
        }
        __syncthreads();
        const int tc = tcnt;
        if (tc <= 256) {
            int p2 = 1; while (p2 < tc) p2 <<= 1;
            for (int t = tid; t < p2; t += 256)
                if (t >= tc) tbuf[t] = ~0ull;
            for (int k = 2; k <= p2; k <<= 1) {
                for (int s = k >> 1; s > 0; s >>= 1) {
                    __syncthreads();
                    for (int t = tid; t < p2; t += 256) {
                        int pr = t ^ s;
                        if (pr > t) {
                            ull a = tbuf[t], bv = tbuf[pr];
                            bool up = ((t & k) == 0);
                            if ((a > bv) == up) { tbuf[t] = bv; tbuf[pr] = a; }
                        }
                    }
                }
            }
            __syncthreads();
            const int need = KK - nless;
            if (tid < need) nbr[nless + tid] = (int)(unsigned)tbuf[tid];
        } else {
            int p2 = KK; while (p2 < c) p2 <<= 1;
            for (int t = tid; t < p2; t += 256)
                if (t >= c) cand[t] = ~0ull;
            for (int k = 2; k <= p2; k <<= 1) {
                for (int s = k >> 1; s > 0; s >>= 1) {
                    __syncthreads();
                    for (int t = tid; t < p2; t += 256) {
                        int pr = t ^ s;
                        if (pr > t) {
                            ull a = cand[t], bv = cand[pr];
                            bool up = ((t & k) == 0);
                            if ((a > bv) == up) { cand[t] = bv; cand[pr] = a; }
                        }
                    }
                }
            }
            __syncthreads();
            if (tid < KK) nbr[tid] = (int)(unsigned)cand[tid];
        }
        if (tid == 0) fincnt = KK;
    }
    __syncthreads();
    const int n = fincnt;

    // ---------------- MLP phase ----------------
    const int ch = tid & 127, half = tid >> 7;
    ull w2p[HH/2];
#pragma unroll
    for (int h = 0; h < HH/2; ++h)
        w2p[h] = pack2(W2[(size_t)(2*h)*CO + ch], W2[(size_t)(2*h + 1)*CO + ch]);

    float mxv = -FLT_MAX;
    for (int jj = 0; jj < n; jj += 4) {
        const int idx = jj + (tid >> 6);
        if (idx < n) {
            const int nb = nbr[idx];
            h1buf[tid >> 6][tid & 63] =
                fmaxf(g_u[((size_t)b*NP + nb)*HH + (tid & 63)] - vsh[tid & 63], 0.0f);
        }
        __syncthreads();
        const int r = half * 2;
        if (jj + r < n)     mxv = fmaxf(mxv, dot64(h1buf[r],     w2p));
        if (jj + r + 1 < n) mxv = fmaxf(mxv, dot64(h1buf[r + 1], w2p));
        __syncthreads();
    }
    if (half == 1) mxsh[ch] = mxv;
    __syncthreads();
    if (half == 0) {
        float o = (n > 1) ? fmaxf(mxv, mxsh[ch]) : mxv;
        out[(size_t)i*CO + ch] = (n > 0) ? (o + b2[ch]) : 0.0f;
    }
}

// =====================================================================================
// tail outputs
// =====================================================================================
__global__ void tail_kernel(float* __restrict__ out, int has_pc, int has_batch) {
    const int i = blockIdx.x * 256 + threadIdx.x;
    if (has_pc && i < MTOT*3) out[(size_t)MTOT*CO + i] = g_pc[i];
    if (has_batch && i < MTOT) out[(size_t)MTOT*CO + (size_t)MTOT*3 + i] = (float)(i / MM);
}

extern "C" void kernel_launch(void* const* d_in, const int* in_sizes, int n_in,
                              void* d_out, int out_size) {
    const float* x   = (const float*)d_in[0];
    const float* pos = (const float*)d_in[1];
    const float* W1  = (const float*)d_in[3];
    const float* b1  = (const float*)d_in[4];
    const float* W2  = (const float*)d_in[5];
    const float* b2  = (const float*)d_in[6];
    float* out = (float*)d_out;

    cudaFuncSetAttribute(fps_kernel, cudaFuncAttributeMaxDynamicSharedMemorySize, 3*NP*4);

    // one-time side stream + fork/join events (resource caching only; per-call work
    // is identical every launch and fully captured into the graph)
    static cudaStream_t s2 = nullptr;
    static cudaEvent_t evFork = nullptr, evJoin = nullptr;
    if (!s2) {
        cudaStreamCreateWithFlags(&s2, cudaStreamNonBlocking);
        cudaEventCreateWithFlags(&evFork, cudaEventDisableTiming);
        cudaEventCreateWithFlags(&evJoin, cudaEventDisableTiming);
    }

    // fork: feat + grid build run concurrently with FPS (they only read inputs)
    cudaEventRecord(evFork, 0);
    cudaStreamWaitEvent(s2, evFork, 0);

    fps_kernel<<<BB*GFPS, TFPS, 3*NP*4>>>(pos);                 // main stream, 16 SMs

    feat_kernel<<<NTOT/4, 256, 0, s2>>>(x, pos, W1, b1);        // side stream
    grid_zero_kernel<<<(BB*CELLS)/256, 256, 0, s2>>>();
    grid_count_kernel<<<NTOT/256, 256, 0, s2>>>(pos);
    grid_scan_kernel<<<1, BB*CELLS, 0, s2>>>();
    grid_scatter_kernel<<<NTOT/256, 256, 0, s2>>>(pos);
    cudaEventRecord(evJoin, s2);

    // join: ballq_mlp needs FPS output (main stream order) + feat/grid (event)
    cudaStreamWaitEvent(0, evJoin, 0);
    ballq_mlp_kernel<<<MTOT, 256>>>(W1, W2, b2, out);

    int has_pc    = out_size >= MTOT*CO + MTOT*3;
    int has_batch = out_size >= MTOT*CO + MTOT*3 + MTOT;
    if (has_pc)
        tail_kernel<<<(MTOT*3 + 255)/256, 256>>>(out, has_pc, has_batch);
}

// round 16
// speedup vs baseline: 1.0757x; 1.0131x over previous
#include <cuda_runtime.h>
#include <math.h>
#include <float.h>

#define BB   2
#define NP   16384
#define FF   32
#define MM   4096
#define KK   64
#define HH   64
#define CO   128
#define NTOT (BB*NP)
#define MTOT (BB*MM)
#define CANDMAX 2048
#define NBIN 2048

#define GFPS  8                 // CTAs per cloud (one cluster)  [proven config]
#define CWARPS 8
#define TFPS  (CWARPS*32)       // 256 threads
#define SHARD (NP/GFPS)
#define PPT   (SHARD/TFPS)      // 8
#define NSLOT (GFPS*CWARPS)     // 64

#define GG    8
#define CELLS (GG*GG*GG)

static __device__ float g_pc[MTOT*3];
static __device__ float g_u[NTOT*HH];
// spatial grid (CSR)
static __device__ int   g_ccnt[BB*CELLS];
static __device__ int   g_coff[BB*CELLS + 1];
static __device__ int   g_cfill[BB*CELLS];
static __device__ float g_gx[NTOT], g_gy[NTOT], g_gz[NTOT];
static __device__ int   g_gidx[NTOT];

typedef unsigned long long ull;

// ---------- packed f32x2 helpers (lane-wise identical rounding to scalar fp32) ----------
__device__ __forceinline__ ull pack2(float lo, float hi) {
    ull r;
    asm("mov.b64 %0, {%1, %2};" : "=l"(r) : "r"(__float_as_uint(lo)), "r"(__float_as_uint(hi)));
    return r;
}
__device__ __forceinline__ void unpack2(ull v, float &lo, float &hi) {
    unsigned a, b;
    asm("mov.b64 {%0, %1}, %2;" : "=r"(a), "=r"(b) : "l"(v));
    lo = __uint_as_float(a); hi = __uint_as_float(b);
}
__device__ __forceinline__ ull add2(ull a, ull b) {
    ull r; asm("add.rn.f32x2 %0, %1, %2;" : "=l"(r) : "l"(a), "l"(b)); return r;
}
__device__ __forceinline__ ull mul2(ull a, ull b) {
    ull r; asm("mul.rn.f32x2 %0, %1, %2;" : "=l"(r) : "l"(a), "l"(b)); return r;
}
__device__ __forceinline__ ull fma2(ull a, ull b, ull c) {
    ull r; asm("fma.rn.f32x2 %0, %1, %2, %3;" : "=l"(r) : "l"(a), "l"(b), "l"(c)); return r;
}

// ---------- cluster / smem sync helpers ----------
__device__ __forceinline__ unsigned cta_rank() {
    unsigned r; asm("mov.u32 %0, %%cluster_ctarank;" : "=r"(r)); return r;
}
__device__ __forceinline__ void cluster_sync_all() {
    asm volatile("barrier.cluster.arrive.aligned;" ::: "memory");
    asm volatile("barrier.cluster.wait.aligned;" ::: "memory");
}
__device__ __forceinline__ unsigned mapa_addr(unsigned local_smem_addr, unsigned target_rank) {
    unsigned raddr;
    asm volatile("mapa.shared::cluster.u32 %0, %1, %2;" : "=r"(raddr)
                 : "r"(local_smem_addr), "r"(target_rank));
    return raddr;
}
__device__ __forceinline__ void st_cluster_relaxed_u64(unsigned remote_addr, ull v) {
    asm volatile("st.relaxed.cluster.shared::cluster.b64 [%0], %1;"
                 :: "r"(remote_addr), "l"(v) : "memory");
}
__device__ __forceinline__ void ld_smem_volatile_v2(unsigned addr, ull &a, ull &b) {
    asm volatile("ld.volatile.shared.v2.u64 {%0, %1}, [%2];"
                 : "=l"(a), "=l"(b) : "r"(addr) : "memory");
}
__device__ __forceinline__ ull umax64(ull a, ull b) { return a > b ? a : b; }

// =====================================================================================
// Kernel 1: exact FPS — R14 structure; key low field inv = 16383-idx (R8-proven):
// equal tags => plain u64 max == larger d, ties -> smaller index (jnp.argmax).
// =====================================================================================
__global__ __launch_bounds__(TFPS, 1) __cluster_dims__(GFPS, 1, 1)
void fps_kernel(const float* __restrict__ pos) {
    extern __shared__ float sh[];
    float* sx = sh;
    float* sy = sh + NP;
    float* sz = sh + 2*NP;
    __shared__ __align__(16) ull slot[2][NSLOT];

    const int tid = threadIdx.x, lane = tid & 31, wid = tid >> 5;
    const unsigned rank = cta_rank();
    const int b = blockIdx.x / GFPS;
    const float* p = pos + (size_t)b * NP * 3;

    const unsigned slot_base = (unsigned)__cvta_generic_to_shared(&slot[0][0]);

    if (tid < 2*NSLOT) slot[tid >> 6][tid & 63] = ~0ull;

    for (int i = tid; i < NP; i += TFPS) {
        sx[i] = p[3*i]; sy[i] = p[3*i+1]; sz[i] = p[3*i+2];
    }
    __syncthreads();
    cluster_sync_all();

    unsigned raddr_g = 0;
    if (lane < GFPS)
        raddr_g = mapa_addr(slot_base + (rank*CWARPS + (unsigned)wid)*8u, (unsigned)lane);

    const int jbase = (int)rank * SHARD + tid;
    float mx[PPT], my[PPT], mz[PPT], d[PPT];
    const float x0 = sx[0], y0 = sy[0], z0 = sz[0];
    float bd = -FLT_MAX; int bj = 0;
#pragma unroll
    for (int k = 0; k < PPT; ++k) {
        int j = jbase + k*TFPS;
        mx[k] = sx[j]; my[k] = sy[j]; mz[k] = sz[j];
        float dx = __fsub_rn(mx[k], x0);
        float dy = __fsub_rn(my[k], y0);
        float dz = __fsub_rn(mz[k], z0);
        d[k] = __fadd_rn(__fadd_rn(__fmul_rn(dx,dx), __fmul_rn(dy,dy)), __fmul_rn(dz,dz));
        if (d[k] > bd) { bd = d[k]; bj = j; }
    }
    if (rank == 0 && tid == 0) {
        g_pc[((size_t)b*MM + 0)*3 + 0] = x0;
        g_pc[((size_t)b*MM + 0)*3 + 1] = y0;
        g_pc[((size_t)b*MM + 0)*3 + 2] = z0;
    }

    for (int m = 1; m < MM; ++m) {
        const int buf = m & 1;
        const unsigned mt = (unsigned)m;
        const unsigned boff = (unsigned)buf * (NSLOT*8u);
        // --- warp reduce: max d-bits, then max inv (== min idx) among tied lanes ---
        const unsigned mb   = __float_as_uint(bd);
        const unsigned wmax = __reduce_max_sync(0xffffffffu, mb);
        const unsigned inv  = 16383u - (unsigned)bj;
        const unsigned ci   = (mb == wmax) ? inv : 0u;
        const unsigned winv = __reduce_max_sync(0xffffffffu, ci);
        const ull key = ((ull)mt << 46) | ((ull)wmax << 14) | winv;
        if (lane < GFPS) st_cluster_relaxed_u64(raddr_g + boff, key);
        // --- poll 64 local slots (2 per lane) until all tagged m ---
        const unsigned sa = slot_base + boff + (unsigned)lane * 16u;
        ull k0, k1;
        for (;;) {
            ld_smem_volatile_v2(sa, k0, k1);
            bool ok = ((unsigned)(k0 >> 46) == mt) & ((unsigned)(k1 >> 46) == mt);
            if (__all_sync(0xffffffffu, ok)) break;
        }
        // --- lane-best: plain u64 max (equal tags, inv encoding) ---
        const ull kb = umax64(k0, k1);
        const unsigned dl = (unsigned)(kb >> 14);
        const unsigned il = (unsigned)(kb & 0x3FFFull);
        const unsigned wd  = __reduce_max_sync(0xffffffffu, dl);
        const unsigned c2  = (dl == wd) ? il : 0u;
        const unsigned wiv = __reduce_max_sync(0xffffffffu, c2);
        const int wj = 16383 - (int)wiv;
        const float wx = sx[wj], wy = sy[wj], wz = sz[wj];
        if (rank == 0 && tid == 0) {
            g_pc[((size_t)b*MM + m)*3 + 0] = wx;
            g_pc[((size_t)b*MM + m)*3 + 1] = wy;
            g_pc[((size_t)b*MM + m)*3 + 2] = wz;
        }
        const ull nwx = pack2(-wx, -wx);
        const ull nwy = pack2(-wy, -wy);
        const ull nwz = pack2(-wz, -wz);
        bd = -FLT_MAX; bj = 0;
#pragma unroll
        for (int kk = 0; kk < PPT/2; ++kk) {
            ull dx = add2(pack2(mx[2*kk], mx[2*kk+1]), nwx);
            ull dy = add2(pack2(my[2*kk], my[2*kk+1]), nwy);
            ull dz = add2(pack2(mz[2*kk], mz[2*kk+1]), nwz);
            ull s  = add2(add2(mul2(dx,dx), mul2(dy,dy)), mul2(dz,dz));
            float s0, s1; unpack2(s, s0, s1);
            d[2*kk]   = fminf(d[2*kk],   s0);
            d[2*kk+1] = fminf(d[2*kk+1], s1);
            if (d[2*kk]   > bd) { bd = d[2*kk];   bj = jbase + (2*kk)*TFPS; }
            if (d[2*kk+1] > bd) { bd = d[2*kk+1]; bj = jbase + (2*kk+1)*TFPS; }
        }
    }
    cluster_sync_all();
}

// =====================================================================================
// Kernel 2: per-point layer-1 partials (unchanged)
// =====================================================================================
__global__ __launch_bounds__(256) void feat_kernel(const float* __restrict__ x,
                                                   const float* __restrict__ pos,
                                                   const float* __restrict__ W1,
                                                   const float* __restrict__ b1) {
    __shared__ float xs[4][FF];
    __shared__ float ps[4][3];
    const int j0 = blockIdx.x * 4;
    const int tid = threadIdx.x;
    if (tid < 128) xs[tid >> 5][tid & 31] = x[(size_t)(j0 + (tid >> 5))*FF + (tid & 31)];
    if (tid < 12)  ps[tid / 3][tid % 3]   = pos[(size_t)j0*3 + tid];
    __syncthreads();
    const int pt = tid >> 6, h = tid & 63;
    float acc = b1[h];
#pragma unroll
    for (int f = 0; f < FF; ++f) acc += xs[pt][f] * W1[f*HH + h];
    acc += ps[pt][0] * W1[32*HH + h];
    acc += ps[pt][1] * W1[33*HH + h];
    acc += ps[pt][2] * W1[34*HH + h];
    g_u[(size_t)(j0 + pt)*HH + h] = acc;
}

// =====================================================================================
// Spatial grid build (unchanged)
// =====================================================================================
__device__ __forceinline__ int cell_of(float x, float y, float z) {
    int cx = min(GG-1, max(0, (int)(x * (float)GG)));
    int cy = min(GG-1, max(0, (int)(y * (float)GG)));
    int cz = min(GG-1, max(0, (int)(z * (float)GG)));
    return (cz*GG + cy)*GG + cx;
}
__global__ void grid_zero_kernel() {
    g_ccnt[blockIdx.x * 256 + threadIdx.x] = 0;
}
__global__ void grid_count_kernel(const float* __restrict__ pos) {
    const int j = blockIdx.x * 256 + threadIdx.x;
    const int b = j / NP;
    atomicAdd(&g_ccnt[b*CELLS + cell_of(pos[3*j], pos[3*j+1], pos[3*j+2])], 1);
}
__global__ __launch_bounds__(1024) void grid_scan_kernel() {
    __shared__ int wtot[32];
    const int tid = threadIdx.x;
    const int lane = tid & 31, w = tid >> 5;
    const int v = g_ccnt[tid];
    int s = v;
#pragma unroll
    for (int o = 1; o < 32; o <<= 1) {
        int n = __shfl_up_sync(0xffffffffu, s, o);
        if (lane >= o) s += n;
    }
    if (lane == 31) wtot[w] = s;
    __syncthreads();
    if (w == 0) {
        int t = wtot[lane], ts = t;
#pragma unroll
        for (int o = 1; o < 32; o <<= 1) {
            int n = __shfl_up_sync(0xffffffffu, ts, o);
            if (lane >= o) ts += n;
        }
        wtot[lane] = ts - t;
    }
    __syncthreads();
    const int excl = s - v + wtot[w];
    g_coff[tid] = excl;
    g_cfill[tid] = excl;
    if (tid == BB*CELLS - 1) g_coff[BB*CELLS] = excl + v;
}
__global__ void grid_scatter_kernel(const float* __restrict__ pos) {
    const int j = blockIdx.x * 256 + threadIdx.x;
    const int b = j / NP, lj = j % NP;
    const float x = pos[3*j], y = pos[3*j+1], z = pos[3*j+2];
    const int slot = atomicAdd(&g_cfill[b*CELLS + cell_of(x, y, z)], 1);
    g_gx[slot] = x; g_gy[slot] = y; g_gz[slot] = z; g_gidx[slot] = lj;
}

// =====================================================================================
// Kernel 3 (FUSED): grid-pruned ball query + radix-select + MLP/max.
// dot64: float4 loads, FULL 16 iterations (64 elems), same a0/a1 pairing as the
// proven float2 version (a0 <- elems 0,1/4,5/...; a1 <- 2,3/6,7/...) => bit-identical.
// =====================================================================================
__device__ __forceinline__ float dot64(const float* __restrict__ h1,
                                       const ull* __restrict__ w2p) {
    const float4* hb = (const float4*)h1;
    ull a0 = 0ull, a1 = 0ull;
#pragma unroll
    for (int q = 0; q < 16; ++q) {          // 16 float4s == 64 floats
        float4 p = hb[q];
        a0 = fma2(pack2(p.x, p.y), w2p[2*q],     a0);
        a1 = fma2(pack2(p.z, p.w), w2p[2*q + 1], a1);
    }
    float l0, u0, l1, u1;
    unpack2(a0, l0, u0); unpack2(a1, l1, u1);
    return (l0 + u0) + (l1 + u1);
}

__global__ __launch_bounds__(256) void ballq_mlp_kernel(const float* __restrict__ W1,
                                                        const float* __restrict__ W2,
                                                        const float* __restrict__ b2,
                                                        float* __restrict__ out) {
    const float R2 = (float)(0.2 * 0.2);
    const int i = blockIdx.x;
    const int b = i / MM;
    __shared__ ull cand[CANDMAX];
    __shared__ int hist[NBIN];
    __shared__ ull tbuf[256];
    __shared__ int nbr[KK];
    __shared__ float vsh[HH];
    __shared__ __align__(16) float h1buf[4][HH];
    __shared__ float mxsh[128];
    __shared__ int cnt, outc, tcnt, tsel_s, nless_s, fincnt;
    __shared__ int wsum[8];
    const int tid = threadIdx.x;
    const int lane = tid & 31, w = tid >> 5;
    if (tid == 0) { cnt = 0; outc = 0; tcnt = 0; }
    const float cx = g_pc[(size_t)i*3 + 0];
    const float cy = g_pc[(size_t)i*3 + 1];
    const float cz = g_pc[(size_t)i*3 + 2];
    for (int t = tid; t < NBIN; t += 256) hist[t] = 0;
    if (tid < HH) {
        float icx = __fdiv_rn(cx, 0.2f);
        float icy = __fdiv_rn(cy, 0.2f);
        float icz = __fdiv_rn(cz, 0.2f);
        vsh[tid] = icx*W1[32*HH + tid] + icy*W1[33*HH + tid] + icz*W1[34*HH + tid];
    }
    __syncthreads();

    // grid-pruned candidate scan, warp-per-row
    const float RW = 0.2001f;
    const int x0 = max(0, (int)floorf((cx - RW) * (float)GG));
    const int x1 = min(GG-1, (int)floorf((cx + RW) * (float)GG));
    const int y0 = max(0, (int)floorf((cy - RW) * (float)GG));
    const int y1 = min(GG-1, (int)floorf((cy + RW) * (float)GG));
    const int z0 = max(0, (int)floorf((cz - RW) * (float)GG));
    const int z1 = min(GG-1, (int)floorf((cz + RW) * (float)GG));
    const int ny = y1 - y0 + 1;
    const int nrows = (z1 - z0 + 1) * ny;
    for (int r = w; r < nrows; r += 8) {
        const int zz = z0 + r / ny;
        const int yy = y0 + r % ny;
        const int cbase = b*CELLS + (zz*GG + yy)*GG;
        const int s0 = g_coff[cbase + x0];
        const int e0 = g_coff[cbase + x1 + 1];
        for (int t = s0 + lane; t < e0; t += 32) {
            float dx = __fsub_rn(cx, g_gx[t]);
            float dy = __fsub_rn(cy, g_gy[t]);
            float dz = __fsub_rn(cz, g_gz[t]);
            float d2 = __fadd_rn(__fadd_rn(__fmul_rn(dx,dx), __fmul_rn(dy,dy)), __fmul_rn(dz,dz));
            if (d2 <= R2) {
                int sl = atomicAdd(&cnt, 1);
                if (sl < CANDMAX)
                    cand[sl] = ((ull)__float_as_uint(d2) << 32) | (unsigned)g_gidx[t];
            }
        }
    }
    __syncthreads();
    const int c = min(cnt, CANDMAX);

    if (c <= KK) {
        for (int s = tid; s < c; s += 256) nbr[s] = (int)(unsigned)cand[s];
        if (tid == 0) fincnt = c;
    } else {
        for (int s = tid; s < c; s += 256)
            atomicAdd(&hist[(unsigned)(cand[s] >> 53)], 1);
        __syncthreads();
        const int base = tid * 8;
        int h[8]; int ssum = 0;
#pragma unroll
        for (int q = 0; q < 8; ++q) { h[q] = hist[base + q]; ssum += h[q]; }
        int v = ssum;
#pragma unroll
        for (int o = 1; o < 32; o <<= 1) {
            int n2 = __shfl_up_sync(0xffffffffu, v, o);
            if (lane >= o) v += n2;
        }
        if (lane == 31) wsum[w] = v;
        __syncthreads();
        if (tid == 0) {
            int a = 0;
#pragma unroll
            for (int q = 0; q < 8; ++q) { int t = wsum[q]; wsum[q] = a; a += t; }
        }
        __syncthreads();
        const int excl = v - ssum + wsum[w];
        if (excl < KK && KK <= excl + ssum) {
            int cum = excl;
#pragma unroll
            for (int q = 0; q < 8; ++q) {
                if (cum < KK && KK <= cum + h[q]) { tsel_s = base + q; nless_s = cum; }
                cum += h[q];
            }
        }
        __syncthreads();
        const int Tbin = tsel_s, nless = nless_s;
        for (int s = tid; s < c; s += 256) {
            const ull cv = cand[s];
            const int bin = (int)(unsigned)(cv >> 53);
            if (bin < Tbin) {
                int o = atomicAdd(&outc, 1);
                nbr[o] = (int)(unsigned)cv;
            } else if (bin == Tbin) {
                int t = atomicAdd(&tcnt, 1);
                if (t < 256) tbuf[t] = cv;
            }
        }
        __syncthreads();
        const int tc = tcnt;
        if (tc <= 256) {
            int p2 = 1; while (p2 < tc) p2 <<= 1;
            for (int t = tid; t < p2; t += 256)
                if (t >= tc) tbuf[t] = ~0ull;
            for (int k = 2; k <= p2; k <<= 1) {
                for (int s = k >> 1; s > 0; s >>= 1) {
                    __syncthreads();
                    for (int t = tid; t < p2; t += 256) {
                        int pr = t ^ s;
                        if (pr > t) {
                            ull a = tbuf[t], bv = tbuf[pr];
                            bool up = ((t & k) == 0);
                            if ((a > bv) == up) { tbuf[t] = bv; tbuf[pr] = a; }
                        }
                    }
                }
            }
            __syncthreads();
            const int need = KK - nless;
            if (tid < need) nbr[nless + tid] = (int)(unsigned)tbuf[tid];
        } else {
            int p2 = KK; while (p2 < c) p2 <<= 1;
            for (int t = tid; t < p2; t += 256)
                if (t >= c) cand[t] = ~0ull;
            for (int k = 2; k <= p2; k <<= 1) {
                for (int s = k >> 1; s > 0; s >>= 1) {
                    __syncthreads();
                    for (int t = tid; t < p2; t += 256) {
                        int pr = t ^ s;
                        if (pr > t) {
                            ull a = cand[t], bv = cand[pr];
                            bool up = ((t & k) == 0);
                            if ((a > bv) == up) { cand[t] = bv; cand[pr] = a; }
                        }
                    }
                }
            }
            __syncthreads();
            if (tid < KK) nbr[tid] = (int)(unsigned)cand[tid];
        }
        if (tid == 0) fincnt = KK;
    }
    __syncthreads();
    const int n = fincnt;

    // ---------------- MLP phase (R14 structure) ----------------
    const int ch = tid & 127, half = tid >> 7;
    ull w2p[HH/2];
#pragma unroll
    for (int h = 0; h < HH/2; ++h)
        w2p[h] = pack2(W2[(size_t)(2*h)*CO + ch], W2[(size_t)(2*h + 1)*CO + ch]);

    float mxv = -FLT_MAX;
    for (int jj = 0; jj < n; jj += 4) {
        const int idx = jj + (tid >> 6);
        if (idx < n) {
            const int nb = nbr[idx];
            h1buf[tid >> 6][tid & 63] =
                fmaxf(g_u[((size_t)b*NP + nb)*HH + (tid & 63)] - vsh[tid & 63], 0.0f);
        }
        __syncthreads();
        const int r = half * 2;
        if (jj + r < n)     mxv = fmaxf(mxv, dot64(h1buf[r],     w2p));
        if (jj + r + 1 < n) mxv = fmaxf(mxv, dot64(h1buf[r + 1], w2p));
        __syncthreads();
    }
    if (half == 1) mxsh[ch] = mxv;
    __syncthreads();
    if (half == 0) {
        float o = (n > 1) ? fmaxf(mxv, mxsh[ch]) : mxv;
        out[(size_t)i*CO + ch] = (n > 0) ? (o + b2[ch]) : 0.0f;
    }
}

// =====================================================================================
// tail outputs
// =====================================================================================
__global__ void tail_kernel(float* __restrict__ out, int has_pc, int has_batch) {
    const int i = blockIdx.x * 256 + threadIdx.x;
    if (has_pc && i < MTOT*3) out[(size_t)MTOT*CO + i] = g_pc[i];
    if (has_batch && i < MTOT) out[(size_t)MTOT*CO + (size_t)MTOT*3 + i] = (float)(i / MM);
}

extern "C" void kernel_launch(void* const* d_in, const int* in_sizes, int n_in,
                              void* d_out, int out_size) {
    const float* x   = (const float*)d_in[0];
    const float* pos = (const float*)d_in[1];
    const float* W1  = (const float*)d_in[3];
    const float* b1  = (const float*)d_in[4];
    const float* W2  = (const float*)d_in[5];
    const float* b2  = (const float*)d_in[6];
    float* out = (float*)d_out;

    cudaFuncSetAttribute(fps_kernel, cudaFuncAttributeMaxDynamicSharedMemorySize, 3*NP*4);

    static cudaStream_t s2 = nullptr;
    static cudaEvent_t evFork = nullptr, evJoin = nullptr;
    if (!s2) {
        cudaStreamCreateWithFlags(&s2, cudaStreamNonBlocking);
        cudaEventCreateWithFlags(&evFork, cudaEventDisableTiming);
        cudaEventCreateWithFlags(&evJoin, cudaEventDisableTiming);
    }

    cudaEventRecord(evFork, 0);
    cudaStreamWaitEvent(s2, evFork, 0);

    fps_kernel<<<BB*GFPS, TFPS, 3*NP*4>>>(pos);                 // main stream, 16 SMs

    feat_kernel<<<NTOT/4, 256, 0, s2>>>(x, pos, W1, b1);        // side stream
    grid_zero_kernel<<<(BB*CELLS)/256, 256, 0, s2>>>();
    grid_count_kernel<<<NTOT/256, 256, 0, s2>>>(pos);
    grid_scan_kernel<<<1, BB*CELLS, 0, s2>>>();
    grid_scatter_kernel<<<NTOT/256, 256, 0, s2>>>(pos);
    cudaEventRecord(evJoin, s2);

    cudaStreamWaitEvent(0, evJoin, 0);
    ballq_mlp_kernel<<<MTOT, 256>>>(W1, W2, b2, out);

    int has_pc    = out_size >= MTOT*CO + MTOT*3;
    int has_batch = out_size >= MTOT*CO + MTOT*3 + MTOT;
    if (has_pc)
        tail_kernel<<<(MTOT*3 + 255)/256, 256>>>(out, has_pc, has_batch);
}

// round 17
// speedup vs baseline: 1.1653x; 1.0832x over previous
#include <cuda_runtime.h>
#include <math.h>
#include <float.h>

#define BB   2
#define NP   16384
#define FF   32
#define MM   4096
#define KK   64
#define HH   64
#define CO   128
#define NTOT (BB*NP)
#define MTOT (BB*MM)
#define CANDMAX 2048
#define NBIN 2048

#define GFPS  8
#define CWARPS 8
#define TFPS  (CWARPS*32)
#define SHARD (NP/GFPS)
#define PPT   (SHARD/TFPS)
#define NSLOT (GFPS*CWARPS)

#define GG    8
#define CELLS (GG*GG*GG)
#define PROG_CHUNK 256

static __device__ float g_pc[MTOT*3];
static __device__ float g_u[NTOT*HH];
static __device__ int   g_prog[BB];
// spatial grid (CSR)
static __device__ int   g_ccnt[BB*CELLS];
static __device__ int   g_coff[BB*CELLS + 1];
static __device__ int   g_cfill[BB*CELLS];
static __device__ float g_gx[NTOT], g_gy[NTOT], g_gz[NTOT];
static __device__ int   g_gidx[NTOT];

typedef unsigned long long ull;

// ---------- packed f32x2 helpers ----------
__device__ __forceinline__ ull pack2(float lo, float hi) {
    ull r;
    asm("mov.b64 %0, {%1, %2};" : "=l"(r) : "r"(__float_as_uint(lo)), "r"(__float_as_uint(hi)));
    return r;
}
__device__ __forceinline__ void unpack2(ull v, float &lo, float &hi) {
    unsigned a, b;
    asm("mov.b64 {%0, %1}, %2;" : "=r"(a), "=r"(b) : "l"(v));
    lo = __uint_as_float(a); hi = __uint_as_float(b);
}
__device__ __forceinline__ ull add2(ull a, ull b) {
    ull r; asm("add.rn.f32x2 %0, %1, %2;" : "=l"(r) : "l"(a), "l"(b)); return r;
}
__device__ __forceinline__ ull mul2(ull a, ull b) {
    ull r; asm("mul.rn.f32x2 %0, %1, %2;" : "=l"(r) : "l"(a), "l"(b)); return r;
}
__device__ __forceinline__ ull fma2(ull a, ull b, ull c) {
    ull r; asm("fma.rn.f32x2 %0, %1, %2, %3;" : "=l"(r) : "l"(a), "l"(b), "l"(c)); return r;
}

// ---------- cluster / sync helpers ----------
__device__ __forceinline__ unsigned cta_rank() {
    unsigned r; asm("mov.u32 %0, %%cluster_ctarank;" : "=r"(r)); return r;
}
__device__ __forceinline__ void cluster_sync_all() {
    asm volatile("barrier.cluster.arrive.aligned;" ::: "memory");
    asm volatile("barrier.cluster.wait.aligned;" ::: "memory");
}
__device__ __forceinline__ unsigned mapa_addr(unsigned local_smem_addr, unsigned target_rank) {
    unsigned raddr;
    asm volatile("mapa.shared::cluster.u32 %0, %1, %2;" : "=r"(raddr)
                 : "r"(local_smem_addr), "r"(target_rank));
    return raddr;
}
__device__ __forceinline__ void st_cluster_relaxed_u64(unsigned remote_addr, ull v) {
    asm volatile("st.relaxed.cluster.shared::cluster.b64 [%0], %1;"
                 :: "r"(remote_addr), "l"(v) : "memory");
}
__device__ __forceinline__ void ld_smem_volatile_v2(unsigned addr, ull &a, ull &b) {
    asm volatile("ld.volatile.shared.v2.u64 {%0, %1}, [%2];"
                 : "=l"(a), "=l"(b) : "r"(addr) : "memory");
}
__device__ __forceinline__ ull umax64(ull a, ull b) { return a > b ? a : b; }
__device__ __forceinline__ void st_release_gpu_s32(int* p, int v) {
    asm volatile("st.release.gpu.global.s32 [%0], %1;" :: "l"(p), "r"(v) : "memory");
}
__device__ __forceinline__ int ld_acquire_gpu_s32(const int* p) {
    int v;
    asm volatile("ld.acquire.gpu.global.s32 %0, [%1];" : "=r"(v) : "l"(p) : "memory");
    return v;
}

__global__ void prog_reset_kernel() {
    if (threadIdx.x < BB) g_prog[threadIdx.x] = 0;
}

// =====================================================================================
// Kernel 1: exact FPS — R16 config + chunked progress publication (16 release stores
// total at m+1 multiples of 256; negligible leader cost, unlike R10's per-iter flag).
// =====================================================================================
__global__ __launch_bounds__(TFPS, 1) __cluster_dims__(GFPS, 1, 1)
void fps_kernel(const float* __restrict__ pos) {
    extern __shared__ float sh[];
    float* sx = sh;
    float* sy = sh + NP;
    float* sz = sh + 2*NP;
    __shared__ __align__(16) ull slot[2][NSLOT];

    const int tid = threadIdx.x, lane = tid & 31, wid = tid >> 5;
    const unsigned rank = cta_rank();
    const int b = blockIdx.x / GFPS;
    const float* p = pos + (size_t)b * NP * 3;

    const unsigned slot_base = (unsigned)__cvta_generic_to_shared(&slot[0][0]);

    if (tid < 2*NSLOT) slot[tid >> 6][tid & 63] = ~0ull;

    for (int i = tid; i < NP; i += TFPS) {
        sx[i] = p[3*i]; sy[i] = p[3*i+1]; sz[i] = p[3*i+2];
    }
    __syncthreads();
    cluster_sync_all();

    unsigned raddr_g = 0;
    if (lane < GFPS)
        raddr_g = mapa_addr(slot_base + (rank*CWARPS + (unsigned)wid)*8u, (unsigned)lane);

    const int jbase = (int)rank * SHARD + tid;
    float mx[PPT], my[PPT], mz[PPT], d[PPT];
    const float x0 = sx[0], y0 = sy[0], z0 = sz[0];
    float bd = -FLT_MAX; int bj = 0;
#pragma unroll
    for (int k = 0; k < PPT; ++k) {
        int j = jbase + k*TFPS;
        mx[k] = sx[j]; my[k] = sy[j]; mz[k] = sz[j];
        float dx = __fsub_rn(mx[k], x0);
        float dy = __fsub_rn(my[k], y0);
        float dz = __fsub_rn(mz[k], z0);
        d[k] = __fadd_rn(__fadd_rn(__fmul_rn(dx,dx), __fmul_rn(dy,dy)), __fmul_rn(dz,dz));
        if (d[k] > bd) { bd = d[k]; bj = j; }
    }
    if (rank == 0 && tid == 0) {
        g_pc[((size_t)b*MM + 0)*3 + 0] = x0;
        g_pc[((size_t)b*MM + 0)*3 + 1] = y0;
        g_pc[((size_t)b*MM + 0)*3 + 2] = z0;
    }

    for (int m = 1; m < MM; ++m) {
        const int buf = m & 1;
        const unsigned mt = (unsigned)m;
        const unsigned boff = (unsigned)buf * (NSLOT*8u);
        const unsigned mb   = __float_as_uint(bd);
        const unsigned wmax = __reduce_max_sync(0xffffffffu, mb);
        const unsigned inv  = 16383u - (unsigned)bj;
        const unsigned ci   = (mb == wmax) ? inv : 0u;
        const unsigned winv = __reduce_max_sync(0xffffffffu, ci);
        const ull key = ((ull)mt << 46) | ((ull)wmax << 14) | winv;
        if (lane < GFPS) st_cluster_relaxed_u64(raddr_g + boff, key);
        const unsigned sa = slot_base + boff + (unsigned)lane * 16u;
        ull k0, k1;
        for (;;) {
            ld_smem_volatile_v2(sa, k0, k1);
            bool ok = ((unsigned)(k0 >> 46) == mt) & ((unsigned)(k1 >> 46) == mt);
            if (__all_sync(0xffffffffu, ok)) break;
        }
        const ull kb = umax64(k0, k1);
        const unsigned dl = (unsigned)(kb >> 14);
        const unsigned il = (unsigned)(kb & 0x3FFFull);
        const unsigned wd  = __reduce_max_sync(0xffffffffu, dl);
        const unsigned c2  = (dl == wd) ? il : 0u;
        const unsigned wiv = __reduce_max_sync(0xffffffffu, c2);
        const int wj = 16383 - (int)wiv;
        const float wx = sx[wj], wy = sy[wj], wz = sz[wj];
        if (rank == 0 && tid == 0) {
            g_pc[((size_t)b*MM + m)*3 + 0] = wx;
            g_pc[((size_t)b*MM + m)*3 + 1] = wy;
            g_pc[((size_t)b*MM + m)*3 + 2] = wz;
            if (((m + 1) & (PROG_CHUNK - 1)) == 0)
                st_release_gpu_s32(&g_prog[b], m + 1);
        }
        const ull nwx = pack2(-wx, -wx);
        const ull nwy = pack2(-wy, -wy);
        const ull nwz = pack2(-wz, -wz);
        bd = -FLT_MAX; bj = 0;
#pragma unroll
        for (int kk = 0; kk < PPT/2; ++kk) {
            ull dx = add2(pack2(mx[2*kk], mx[2*kk+1]), nwx);
            ull dy = add2(pack2(my[2*kk], my[2*kk+1]), nwy);
            ull dz = add2(pack2(mz[2*kk], mz[2*kk+1]), nwz);
            ull s  = add2(add2(mul2(dx,dx), mul2(dy,dy)), mul2(dz,dz));
            float s0, s1; unpack2(s, s0, s1);
            d[2*kk]   = fminf(d[2*kk],   s0);
            d[2*kk+1] = fminf(d[2*kk+1], s1);
            if (d[2*kk]   > bd) { bd = d[2*kk];   bj = jbase + (2*kk)*TFPS; }
            if (d[2*kk+1] > bd) { bd = d[2*kk+1]; bj = jbase + (2*kk+1)*TFPS; }
        }
    }
    cluster_sync_all();
}

// =====================================================================================
// Kernel 2: per-point layer-1 partials (unchanged)
// =====================================================================================
__global__ __launch_bounds__(256) void feat_kernel(const float* __restrict__ x,
                                                   const float* __restrict__ pos,
                                                   const float* __restrict__ W1,
                                                   const float* __restrict__ b1) {
    __shared__ float xs[4][FF];
    __shared__ float ps[4][3];
    const int j0 = blockIdx.x * 4;
    const int tid = threadIdx.x;
    if (tid < 128) xs[tid >> 5][tid & 31] = x[(size_t)(j0 + (tid >> 5))*FF + (tid & 31)];
    if (tid < 12)  ps[tid / 3][tid % 3]   = pos[(size_t)j0*3 + tid];
    __syncthreads();
    const int pt = tid >> 6, h = tid & 63;
    float acc = b1[h];
#pragma unroll
    for (int f = 0; f < FF; ++f) acc += xs[pt][f] * W1[f*HH + h];
    acc += ps[pt][0] * W1[32*HH + h];
    acc += ps[pt][1] * W1[33*HH + h];
    acc += ps[pt][2] * W1[34*HH + h];
    g_u[(size_t)(j0 + pt)*HH + h] = acc;
}

// =====================================================================================
// Spatial grid build (unchanged)
// =====================================================================================
__device__ __forceinline__ int cell_of(float x, float y, float z) {
    int cx = min(GG-1, max(0, (int)(x * (float)GG)));
    int cy = min(GG-1, max(0, (int)(y * (float)GG)));
    int cz = min(GG-1, max(0, (int)(z * (float)GG)));
    return (cz*GG + cy)*GG + cx;
}
__global__ void grid_zero_kernel() {
    g_ccnt[blockIdx.x * 256 + threadIdx.x] = 0;
}
__global__ void grid_count_kernel(const float* __restrict__ pos) {
    const int j = blockIdx.x * 256 + threadIdx.x;
    const int b = j / NP;
    atomicAdd(&g_ccnt[b*CELLS + cell_of(pos[3*j], pos[3*j+1], pos[3*j+2])], 1);
}
__global__ __launch_bounds__(1024) void grid_scan_kernel() {
    __shared__ int wtot[32];
    const int tid = threadIdx.x;
    const int lane = tid & 31, w = tid >> 5;
    const int v = g_ccnt[tid];
    int s = v;
#pragma unroll
    for (int o = 1; o < 32; o <<= 1) {
        int n = __shfl_up_sync(0xffffffffu, s, o);
        if (lane >= o) s += n;
    }
    if (lane == 31) wtot[w] = s;
    __syncthreads();
    if (w == 0) {
        int t = wtot[lane], ts = t;
#pragma unroll
        for (int o = 1; o < 32; o <<= 1) {
            int n = __shfl_up_sync(0xffffffffu, ts, o);
            if (lane >= o) ts += n;
        }
        wtot[lane] = ts - t;
    }
    __syncthreads();
    const int excl = s - v + wtot[w];
    g_coff[tid] = excl;
    g_cfill[tid] = excl;
    if (tid == BB*CELLS - 1) g_coff[BB*CELLS] = excl + v;
}
__global__ void grid_scatter_kernel(const float* __restrict__ pos) {
    const int j = blockIdx.x * 256 + threadIdx.x;
    const int b = j / NP, lj = j % NP;
    const float x = pos[3*j], y = pos[3*j+1], z = pos[3*j+2];
    const int slot = atomicAdd(&g_cfill[b*CELLS + cell_of(x, y, z)], 1);
    g_gx[slot] = x; g_gy[slot] = y; g_gz[slot] = z; g_gidx[slot] = lj;
}

// =====================================================================================
// Kernel 3 (FUSED, now CONCURRENT with FPS): waits for its centroid's progress chunk,
// then grid-pruned ball query + radix-select + MLP/max (R16 code).
// =====================================================================================
__device__ __forceinline__ float dot64(const float* __restrict__ h1,
                                       const ull* __restrict__ w2p) {
    const float4* hb = (const float4*)h1;
    ull a0 = 0ull, a1 = 0ull;
#pragma unroll
    for (int q = 0; q < 16; ++q) {
        float4 p = hb[q];
        a0 = fma2(pack2(p.x, p.y), w2p[2*q],     a0);
        a1 = fma2(pack2(p.z, p.w), w2p[2*q + 1], a1);
    }
    float l0, u0, l1, u1;
    unpack2(a0, l0, u0); unpack2(a1, l1, u1);
    return (l0 + u0) + (l1 + u1);
}

__global__ __launch_bounds__(256) void ballq_mlp_kernel(const float* __restrict__ W1,
                                                        const float* __restrict__ W2,
                                                        const float* __restrict__ b2,
                                                        float* __restrict__ out) {
    const float R2 = (float)(0.2 * 0.2);
    const int i = blockIdx.x;
    const int b = i / MM, ilocal = i % MM;
    __shared__ ull cand[CANDMAX];
    __shared__ int hist[NBIN];
    __shared__ ull tbuf[256];
    __shared__ int nbr[KK];
    __shared__ float vsh[HH];
    __shared__ __align__(16) float h1buf[4][HH];
    __shared__ float mxsh[128];
    __shared__ int cnt, outc, tcnt, tsel_s, nless_s, fincnt;
    __shared__ int wsum[8];
    const int tid = threadIdx.x;
    const int lane = tid & 31, w = tid >> 5;
    if (tid == 0) { cnt = 0; outc = 0; tcnt = 0; }
    for (int t = tid; t < NBIN; t += 256) hist[t] = 0;

    // preload W2 column while (possibly) waiting
    const int ch = tid & 127, half = tid >> 7;
    ull w2p[HH/2];
#pragma unroll
    for (int h = 0; h < HH/2; ++h)
        w2p[h] = pack2(W2[(size_t)(2*h)*CO + ch], W2[(size_t)(2*h + 1)*CO + ch]);

    // wait until FPS has published our centroid's chunk
    if (tid == 0) {
        while (ld_acquire_gpu_s32(&g_prog[b]) <= ilocal) __nanosleep(256);
    }
    __syncthreads();

    const float cx = __ldcg(&g_pc[(size_t)i*3 + 0]);
    const float cy = __ldcg(&g_pc[(size_t)i*3 + 1]);
    const float cz = __ldcg(&g_pc[(size_t)i*3 + 2]);
    if (tid < HH) {
        float icx = __fdiv_rn(cx, 0.2f);
        float icy = __fdiv_rn(cy, 0.2f);
        float icz = __fdiv_rn(cz, 0.2f);
        vsh[tid] = icx*W1[32*HH + tid] + icy*W1[33*HH + tid] + icz*W1[34*HH + tid];
    }
    __syncthreads();

    // grid-pruned candidate scan, warp-per-row
    const float RW = 0.2001f;
    const int x0 = max(0, (int)floorf((cx - RW) * (float)GG));
    const int x1 = min(GG-1, (int)floorf((cx + RW) * (float)GG));
    const int y0 = max(0, (int)floorf((cy - RW) * (float)GG));
    const int y1 = min(GG-1, (int)floorf((cy + RW) * (float)GG));
    const int z0 = max(0, (int)floorf((cz - RW) * (float)GG));
    const int z1 = min(GG-1, (int)floorf((cz + RW) * (float)GG));
    const int ny = y1 - y0 + 1;
    const int nrows = (z1 - z0 + 1) * ny;
    for (int r = w; r < nrows; r += 8) {
        const int zz = z0 + r / ny;
        const int yy = y0 + r % ny;
        const int cbase = b*CELLS + (zz*GG + yy)*GG;
        const int s0 = g_coff[cbase + x0];
        const int e0 = g_coff[cbase + x1 + 1];
        for (int t = s0 + lane; t < e0; t += 32) {
            float dx = __fsub_rn(cx, g_gx[t]);
            float dy = __fsub_rn(cy, g_gy[t]);
            float dz = __fsub_rn(cz, g_gz[t]);
            float d2 = __fadd_rn(__fadd_rn(__fmul_rn(dx,dx), __fmul_rn(dy,dy)), __fmul_rn(dz,dz));
            if (d2 <= R2) {
                int sl = atomicAdd(&cnt, 1);
                if (sl < CANDMAX)
                    cand[sl] = ((ull)__float_as_uint(d2) << 32) | (unsigned)g_gidx[t];
            }
        }
    }
    __syncthreads();
    const int c = min(cnt, CANDMAX);

    if (c <= KK) {
        for (int s = tid; s < c; s += 256) nbr[s] = (int)(unsigned)cand[s];
        if (tid == 0) fincnt = c;
    } else {
        for (int s = tid; s < c; s += 256)
            atomicAdd(&hist[(unsigned)(cand[s] >> 53)], 1);
        __syncthreads();
        const int base = tid * 8;
        int h[8]; int ssum = 0;
#pragma unroll
        for (int q = 0; q < 8; ++q) { h[q] = hist[base + q]; ssum += h[q]; }
        int v = ssum;
#pragma unroll
        for (int o = 1; o < 32; o <<= 1) {
            int n2 = __shfl_up_sync(0xffffffffu, v, o);
            if (lane >= o) v += n2;
        }
        if (lane == 31) wsum[w] = v;
        __syncthreads();
        if (tid == 0) {
            int a = 0;
#pragma unroll
            for (int q = 0; q < 8; ++q) { int t = wsum[q]; wsum[q] = a; a += t; }
        }
        __syncthreads();
        const int excl = v - ssum + wsum[w];
        if (excl < KK && KK <= excl + ssum) {
            int cum = excl;
#pragma unroll
            for (int q = 0; q < 8; ++q) {
                if (cum < KK && KK <= cum + h[q]) { tsel_s = base + q; nless_s = cum; }
                cum += h[q];
            }
        }
        __syncthreads();
        const int Tbin = tsel_s, nless = nless_s;
        for (int s = tid; s < c; s += 256) {
            const ull cv = cand[s];
            const int bin = (int)(unsigned)(cv >> 53);
            if (bin < Tbin) {
                int o = atomicAdd(&outc, 1);
                nbr[o] = (int)(unsigned)cv;
            } else if (bin == Tbin) {
                int t = atomicAdd(&tcnt, 1);
                if (t < 256) tbuf[t] = cv;
            }
        }
        __syncthreads();
        const int tc = tcnt;
        if (tc <= 256) {
            int p2 = 1; while (p2 < tc) p2 <<= 1;
            for (int t = tid; t < p2; t += 256)
                if (t >= tc) tbuf[t] = ~0ull;
            for (int k = 2; k <= p2; k <<= 1) {
                for (int s = k >> 1; s > 0; s >>= 1) {
                    __syncthreads();
                    for (int t = tid; t < p2; t += 256) {
                        int pr = t ^ s;
                        if (pr > t) {
                            ull a = tbuf[t], bv = tbuf[pr];
                            bool up = ((t & k) == 0);
                            if ((a > bv) == up) { tbuf[t] = bv; tbuf[pr] = a; }
                        }
                    }
                }
            }
            __syncthreads();
            const int need = KK - nless;
            if (tid < need) nbr[nless + tid] = (int)(unsigned)tbuf[tid];
        } else {
            int p2 = KK; while (p2 < c) p2 <<= 1;
            for (int t = tid; t < p2; t += 256)
                if (t >= c) cand[t] = ~0ull;
            for (int k = 2; k <= p2; k <<= 1) {
                for (int s = k >> 1; s > 0; s >>= 1) {
                    __syncthreads();
                    for (int t = tid; t < p2; t += 256) {
                        int pr = t ^ s;
                        if (pr > t) {
                            ull a = cand[t], bv = cand[pr];
                            bool up = ((t & k) == 0);
                            if ((a > bv) == up) { cand[t] = bv; cand[pr] = a; }
                        }
                    }
                }
            }
            __syncthreads();
            if (tid < KK) nbr[tid] = (int)(unsigned)cand[tid];
        }
        if (tid == 0) fincnt = KK;
    }
    __syncthreads();
    const int n = fincnt;

    // ---------------- MLP phase ----------------
    float mxv = -FLT_MAX;
    for (int jj = 0; jj < n; jj += 4) {
        const int idx = jj + (tid >> 6);
        if (idx < n) {
            const int nb = nbr[idx];
            h1buf[tid >> 6][tid & 63] =
                fmaxf(g_u[((size_t)b*NP + nb)*HH + (tid & 63)] - vsh[tid & 63], 0.0f);
        }
        __syncthreads();
        const int r = half * 2;
        if (jj + r < n)     mxv = fmaxf(mxv, dot64(h1buf[r],     w2p));
        if (jj + r + 1 < n) mxv = fmaxf(mxv, dot64(h1buf[r + 1], w2p));
        __syncthreads();
    }
    if (half == 1) mxsh[ch] = mxv;
    __syncthreads();
    if (half == 0) {
        float o = (n > 1) ? fmaxf(mxv, mxsh[ch]) : mxv;
        out[(size_t)i*CO + ch] = (n > 0) ? (o + b2[ch]) : 0.0f;
    }
}

// =====================================================================================
// tail outputs
// =====================================================================================
__global__ void tail_kernel(float* __restrict__ out, int has_pc, int has_batch) {
    const int i = blockIdx.x * 256 + threadIdx.x;
    if (has_pc && i < MTOT*3) out[(size_t)MTOT*CO + i] = g_pc[i];
    if (has_batch && i < MTOT) out[(size_t)MTOT*CO + (size_t)MTOT*3 + i] = (float)(i / MM);
}

extern "C" void kernel_launch(void* const* d_in, const int* in_sizes, int n_in,
                              void* d_out, int out_size) {
    const float* x   = (const float*)d_in[0];
    const float* pos = (const float*)d_in[1];
    const float* W1  = (const float*)d_in[3];
    const float* b1  = (const float*)d_in[4];
    const float* W2  = (const float*)d_in[5];
    const float* b2  = (const float*)d_in[6];
    float* out = (float*)d_out;

    cudaFuncSetAttribute(fps_kernel, cudaFuncAttributeMaxDynamicSharedMemorySize, 3*NP*4);

    static cudaStream_t s2 = nullptr;
    static cudaEvent_t evFork = nullptr, evJoin = nullptr;
    if (!s2) {
        cudaStreamCreateWithFlags(&s2, cudaStreamNonBlocking);
        cudaEventCreateWithFlags(&evFork, cudaEventDisableTiming);
        cudaEventCreateWithFlags(&evJoin, cudaEventDisableTiming);
    }

    // main stream: reset progress, then FPS
    prog_reset_kernel<<<1, 32>>>();

    cudaEventRecord(evFork, 0);
    cudaStreamWaitEvent(s2, evFork, 0);

    fps_kernel<<<BB*GFPS, TFPS, 3*NP*4>>>(pos);                 // main stream, 16 SMs

    // side stream: feat + grid build, then consumers (concurrent with FPS,
    // synchronized per-centroid via g_prog). 14KB smem pad blocks co-residency
    // with FPS CTAs so FPS keeps its SMs.
    feat_kernel<<<NTOT/4, 256, 0, s2>>>(x, pos, W1, b1);
    grid_zero_kernel<<<(BB*CELLS)/256, 256, 0, s2>>>();
    grid_count_kernel<<<NTOT/256, 256, 0, s2>>>(pos);
    grid_scan_kernel<<<1, BB*CELLS, 0, s2>>>();
    grid_scatter_kernel<<<NTOT/256, 256, 0, s2>>>(pos);
    ballq_mlp_kernel<<<MTOT, 256, 14*1024, s2>>>(W1, W2, b2, out);
    cudaEventRecord(evJoin, s2);

    // join side stream back before tail (and before graph end)
    cudaStreamWaitEvent(0, evJoin, 0);

    int has_pc    = out_size >= MTOT*CO + MTOT*3;
    int has_batch = out_size >= MTOT*CO + MTOT*3 + MTOT;
    if (has_pc)
        tail_kernel<<<(MTOT*3 + 255)/256, 256>>>(out, has_pc, has_batch);
}